// round 8
// baseline (speedup 1.0000x reference)
#include <cuda_runtime.h>

// NeuralODE fused RK4 persistent kernel — fully-coalesced minimal-L1 version.
// B=1024, D=256, H=1024, 8 RK4 steps (32 MLP evals). 128 CTAs x 512 threads.
//
// W1 and W2 each read exactly once per CTA per eval, and every weight LDG.128
// covers full 128B lines (8 contiguous lanes x 16B per j/d row):
//  phase1: cols = two blocks (oc8, oc8+128), d-split 4-way in lane bits 3-4,
//          2-round shfl reduce-scatter.
//  phase2: u2-col = 8 warp-groups x 8 lanes, j-split = 4-way in lanes (shfl)
//          x 2-way across warps (one 8KB smem exchange through s_probe).

namespace {
constexpr int Dn     = 256;
constexpr int Hn     = 1024;
constexpr int NSTEPS = 8;
constexpr int MBLK   = 8;
constexpr int NTHR   = 512;
constexpr int GRID   = 128;   // 1024 rows / 8
}

using ull = unsigned long long;

__device__ __forceinline__ float tanha(float x) {
    float y;
    asm("tanh.approx.f32 %0, %1;" : "=f"(y) : "f"(x));
    return y;
}

__device__ __forceinline__ ull dup2(float x) {
    ull r;
    asm("mov.b64 %0, {%1, %1};" : "=l"(r) : "f"(x));
    return r;
}

__device__ __forceinline__ ull pk2(float lo, float hi) {
    ull r;
    asm("mov.b64 %0, {%1, %2};" : "=l"(r) : "f"(lo), "f"(hi));
    return r;
}

__device__ __forceinline__ void unpk2(ull p, float& lo, float& hi) {
    asm("mov.b64 {%0, %1}, %2;" : "=f"(lo), "=f"(hi) : "l"(p));
}

__device__ __forceinline__ ull fma2(ull a, ull b, ull c) {
    ull d;
    asm("fma.rn.f32x2 %0, %1, %2, %3;" : "=l"(d) : "l"(a), "l"(b), "l"(c));
    return d;
}

__device__ __forceinline__ ull add2(ull a, ull b) {
    ull d;
    asm("add.rn.f32x2 %0, %1, %2;" : "=l"(d) : "l"(a), "l"(b));
    return d;
}

__device__ __forceinline__ ull shfl_xor64(ull v, int m) {
    return __shfl_xor_sync(0xffffffffu, v, m);
}

__device__ __forceinline__ float4 f4_axpy(float a, float4 x, float4 y) {
    float4 r;
    r.x = fmaf(a, x.x, y.x);
    r.y = fmaf(a, x.y, y.y);
    r.z = fmaf(a, x.z, y.z);
    r.w = fmaf(a, x.w, y.w);
    return r;
}

__device__ __forceinline__ float4 f4_add(float4 a, float4 b) {
    float4 r; r.x = a.x + b.x; r.y = a.y + b.y; r.z = a.z + b.z; r.w = a.w + b.w; return r;
}

__global__ void __launch_bounds__(NTHR, 1) node_rk4_kernel(
    const float* __restrict__ z0, const float* __restrict__ tt,
    const float* __restrict__ W1, const float* __restrict__ b1,
    const float* __restrict__ W2, const float* __restrict__ b2,
    float* __restrict__ out)
{
    __shared__ __align__(16) float s_probe[MBLK][Dn];   //  8 KB (also jhalf-exchange scratch)
    __shared__ __align__(16) float s_hid[MBLK][Hn];     // 32 KB

    const int tid  = threadIdx.x;
    const int row0 = blockIdx.x * MBLK;

    const float h  = (tt[1] - tt[0]) / (float)NSTEPS;
    const float h2 = 0.5f * h;
    const float h6 = h * (1.0f / 6.0f);

    const int warp = tid >> 5;
    const int lane = tid & 31;

    // phase-1 ownership: col blocks oc8 / oc8+128 (f4 units), d-quarter dq
    const int oc8 = warp * 8 + (lane & 7);     // 0..127
    const int dq  = lane >> 3;                 // 0..3
    // phase-2 ownership: u2 col c2, j-quarter (jhalf from warp, jq from lanes)
    const int c2    = (warp & 7) * 8 + (lane & 7);   // 0..63
    const int jhalf = warp >> 3;                     // 0/1
    const int jq    = lane >> 3;                     // 0..3
    // reduce-scatter row targets (shared by both phases; lane bits 3,4)
    const int b3h = (lane >> 3) & 1;
    const int b4h = (lane >> 4) & 1;
    const int r0  = 4 * b3h + 2 * b4h;               // lane owns rows r0, r0+1

    const ulonglong2* __restrict__ W1u2 = reinterpret_cast<const ulonglong2*>(W1);
    const ulonglong2* __restrict__ W2u2 = reinterpret_cast<const ulonglong2*>(W2);
    const float4* __restrict__ b1f4 = reinterpret_cast<const float4*>(b1);
    const float4* __restrict__ b2f4 = reinterpret_cast<const float4*>(b2);

    // glue state (jhalf==0 lanes only): rows r0, r0+1, f4 col c2
    float4 zb[2], ac[2];
    if (jhalf == 0) {
        zb[0] = reinterpret_cast<const float4*>(z0)[(row0 + r0)     * (Dn / 4) + c2];
        zb[1] = reinterpret_cast<const float4*>(z0)[(row0 + r0 + 1) * (Dn / 4) + c2];
        *reinterpret_cast<float4*>(&s_probe[r0][4 * c2])     = zb[0];
        *reinterpret_cast<float4*>(&s_probe[r0 + 1][4 * c2]) = zb[1];
    }
    __syncthreads();

// phase-1 inner: one d value (weights wAx/wBx), component `comp` of zr
#define P1DD(comp, WA, WB)                                                       \
    do {                                                                         \
        const ull zd = dup2(zr.comp);                                            \
        a[r][0] = fma2(zd, WA.x, a[r][0]);                                       \
        a[r][1] = fma2(zd, WA.y, a[r][1]);                                       \
        a[r][2] = fma2(zd, WB.x, a[r][2]);                                       \
        a[r][3] = fma2(zd, WB.y, a[r][3]);                                       \
    } while (0)

// phase-2 inner: one j value (weights wvx), component `comp` of hv
#define P2JJ(comp, WV)                                                           \
    do {                                                                         \
        const ull hd = dup2(hv.comp);                                            \
        k[r][0] = fma2(hd, WV.x, k[r][0]);                                       \
        k[r][1] = fma2(hd, WV.y, k[r][1]);                                       \
    } while (0)

    for (int step = 0; step < NSTEPS; ++step) {
        #pragma unroll
        for (int e = 0; e < 4; ++e) {
            // ================= phase 1: hid = tanh(probe @ W1 + b1) =========
            // thread: f4 cols {oc8, oc8+128}, all 8 rows, d in quarter dq.
            ull a[8][4];
            {
                ull i0 = 0, i1 = 0, i2 = 0, i3 = 0;
                if (dq == 0) {   // bias counted once via dq==0 partial
                    const float4 bA = b1f4[oc8];
                    const float4 bB = b1f4[oc8 + 128];
                    i0 = pk2(bA.x, bA.y); i1 = pk2(bA.z, bA.w);
                    i2 = pk2(bB.x, bB.y); i3 = pk2(bB.z, bB.w);
                }
                #pragma unroll
                for (int r = 0; r < 8; ++r) { a[r][0] = i0; a[r][1] = i1; a[r][2] = i2; a[r][3] = i3; }
            }

            for (int c4 = 0; c4 < 16; ++c4) {
                const int dF4 = dq * 16 + c4;          // f4 index into D
                const int wrow = 4 * dF4;
                const ulonglong2 wA0 = W1u2[(wrow + 0) * 256 + oc8];
                const ulonglong2 wB0 = W1u2[(wrow + 0) * 256 + oc8 + 128];
                const ulonglong2 wA1 = W1u2[(wrow + 1) * 256 + oc8];
                const ulonglong2 wB1 = W1u2[(wrow + 1) * 256 + oc8 + 128];
                const ulonglong2 wA2 = W1u2[(wrow + 2) * 256 + oc8];
                const ulonglong2 wB2 = W1u2[(wrow + 2) * 256 + oc8 + 128];
                const ulonglong2 wA3 = W1u2[(wrow + 3) * 256 + oc8];
                const ulonglong2 wB3 = W1u2[(wrow + 3) * 256 + oc8 + 128];
                #pragma unroll
                for (int r = 0; r < 8; ++r) {
                    const float4 zr = *reinterpret_cast<const float4*>(&s_probe[r][4 * dF4]);
                    P1DD(x, wA0, wB0);
                    P1DD(y, wA1, wB1);
                    P1DD(z, wA2, wB2);
                    P1DD(w, wA3, wB3);
                }
            }

            // reduce-scatter over dq: xor 8 then xor 16; lane keeps rows r0, r0+1
            ull t2[2][4];
            {
                ull t4[4][4];
                #pragma unroll
                for (int i = 0; i < 4; ++i) {
                    #pragma unroll
                    for (int p = 0; p < 4; ++p) {
                        const ull keep = b3h ? a[4 + i][p] : a[i][p];
                        const ull send = b3h ? a[i][p] : a[4 + i][p];
                        t4[i][p] = add2(keep, shfl_xor64(send, 8));
                    }
                }
                #pragma unroll
                for (int u = 0; u < 2; ++u) {
                    #pragma unroll
                    for (int p = 0; p < 4; ++p) {
                        const ull keep = b4h ? t4[2 + u][p] : t4[u][p];
                        const ull send = b4h ? t4[u][p] : t4[2 + u][p];
                        t2[u][p] = add2(keep, shfl_xor64(send, 16));
                    }
                }
            }

            #pragma unroll
            for (int rr = 0; rr < 2; ++rr) {
                float u0, u1, u2, u3, u4, u5, u6, u7;
                unpk2(t2[rr][0], u0, u1); unpk2(t2[rr][1], u2, u3);
                unpk2(t2[rr][2], u4, u5); unpk2(t2[rr][3], u6, u7);
                const float4 tA = make_float4(tanha(u0), tanha(u1), tanha(u2), tanha(u3));
                const float4 tB = make_float4(tanha(u4), tanha(u5), tanha(u6), tanha(u7));
                *reinterpret_cast<float4*>(&s_hid[r0 + rr][4 * oc8])         = tA;
                *reinterpret_cast<float4*>(&s_hid[r0 + rr][4 * (oc8 + 128)]) = tB;
            }
            __syncthreads();

            // ================= phase 2: k = hid @ W2 + b2 ====================
            // thread: u2 col c2, all 8 rows, j in quarter (jhalf, jq).
            ull k[8][2];
            {
                ull i0 = 0, i1 = 0;
                if (jhalf == 0 && jq == 0) {
                    const float4 bv = b2f4[c2];
                    i0 = pk2(bv.x, bv.y); i1 = pk2(bv.z, bv.w);
                }
                #pragma unroll
                for (int r = 0; r < 8; ++r) { k[r][0] = i0; k[r][1] = i1; }
            }

            #pragma unroll 2
            for (int c4 = 0; c4 < 32; ++c4) {
                const int f4i = jhalf * 128 + c4 * 4 + jq;   // f4 index into H
                const int jr = 4 * f4i;
                const ulonglong2 wv0 = W2u2[(jr + 0) * 64 + c2];
                const ulonglong2 wv1 = W2u2[(jr + 1) * 64 + c2];
                const ulonglong2 wv2 = W2u2[(jr + 2) * 64 + c2];
                const ulonglong2 wv3 = W2u2[(jr + 3) * 64 + c2];
                #pragma unroll
                for (int r = 0; r < 8; ++r) {
                    const float4 hv = *reinterpret_cast<const float4*>(&s_hid[r][4 * f4i]);
                    P2JJ(x, wv0);
                    P2JJ(y, wv1);
                    P2JJ(z, wv2);
                    P2JJ(w, wv3);
                }
            }

            // reduce-scatter over jq (xor 8, xor 16): lane keeps rows r0, r0+1
            ull s2[2][2];
            {
                ull s4[4][2];
                #pragma unroll
                for (int i = 0; i < 4; ++i) {
                    #pragma unroll
                    for (int p = 0; p < 2; ++p) {
                        const ull keep = b3h ? k[4 + i][p] : k[i][p];
                        const ull send = b3h ? k[i][p] : k[4 + i][p];
                        s4[i][p] = add2(keep, shfl_xor64(send, 8));
                    }
                }
                #pragma unroll
                for (int u = 0; u < 2; ++u) {
                    #pragma unroll
                    for (int p = 0; p < 2; ++p) {
                        const ull keep = b4h ? s4[2 + u][p] : s4[u][p];
                        const ull send = b4h ? s4[u][p] : s4[2 + u][p];
                        s2[u][p] = add2(keep, shfl_xor64(send, 16));
                    }
                }
            }

            // cross-warp jhalf exchange via s_probe scratch (u2[8][64])
            ulonglong2* sp = reinterpret_cast<ulonglong2*>(&s_probe[0][0]);
            if (jhalf == 1) {
                sp[r0 * 64 + c2]       = make_ulonglong2(s2[0][0], s2[0][1]);
                sp[(r0 + 1) * 64 + c2] = make_ulonglong2(s2[1][0], s2[1][1]);
            }
            __syncthreads();

            if (jhalf == 0) {
                const ulonglong2 p0 = sp[r0 * 64 + c2];
                const ulonglong2 p1 = sp[(r0 + 1) * 64 + c2];
                s2[0][0] = add2(s2[0][0], p0.x); s2[0][1] = add2(s2[0][1], p0.y);
                s2[1][0] = add2(s2[1][0], p1.x); s2[1][1] = add2(s2[1][1], p1.y);

                float4 kk[2];
                unpk2(s2[0][0], kk[0].x, kk[0].y); unpk2(s2[0][1], kk[0].z, kk[0].w);
                unpk2(s2[1][0], kk[1].x, kk[1].y); unpk2(s2[1][1], kk[1].z, kk[1].w);

                // ---------- RK4 elementwise glue (rows r0, r0+1) ----------
                #pragma unroll
                for (int rr = 0; rr < 2; ++rr) {
                    float4 p;
                    if (e == 0) {
                        ac[rr] = kk[rr];
                        p      = f4_axpy(h2, kk[rr], zb[rr]);
                    } else if (e == 1) {
                        ac[rr] = f4_axpy(2.0f, kk[rr], ac[rr]);
                        p      = f4_axpy(h2, kk[rr], zb[rr]);
                    } else if (e == 2) {
                        ac[rr] = f4_axpy(2.0f, kk[rr], ac[rr]);
                        p      = f4_axpy(h, kk[rr], zb[rr]);
                    } else {
                        ac[rr] = f4_add(ac[rr], kk[rr]);
                        zb[rr] = f4_axpy(h6, ac[rr], zb[rr]);
                        p      = zb[rr];
                    }
                    *reinterpret_cast<float4*>(&s_probe[r0 + rr][4 * c2]) = p;
                }
            }
            __syncthreads();
        }
    }

    if (jhalf == 0) {
        reinterpret_cast<float4*>(out)[(row0 + r0)     * (Dn / 4) + c2] = zb[0];
        reinterpret_cast<float4*>(out)[(row0 + r0 + 1) * (Dn / 4) + c2] = zb[1];
    }

#undef P1DD
#undef P2JJ
}

extern "C" void kernel_launch(void* const* d_in, const int* in_sizes, int n_in,
                              void* d_out, int out_size) {
    const float* z0 = (const float*)d_in[0];
    const float* tt = (const float*)d_in[1];
    const float* W1 = (const float*)d_in[2];
    const float* b1 = (const float*)d_in[3];
    const float* W2 = (const float*)d_in[4];
    const float* b2 = (const float*)d_in[5];
    float* out = (float*)d_out;
    (void)in_sizes; (void)n_in; (void)out_size;

    node_rk4_kernel<<<GRID, NTHR>>>(z0, tt, W1, b1, W2, b2, out);
}